// round 11
// baseline (speedup 1.0000x reference)
#include <cuda_runtime.h>
#include <cuda_fp16.h>
#include <cuda_bf16.h>
#include <cstdint>
#include <cstddef>

#define N_NODES 100000
#define N_EDGES 3200000
#define FEAT 256
#define FEAT8 (FEAT / 8)          // uint4 (8 halves) units per row = 32
#define EPS 1e-12f
#define SCAN_B 1024
#define SCAN_NB ((N_NODES + SCAN_B - 1) / SCAN_B)   // 98

// ---------------- device scratch (no allocations allowed) ----------------
__device__ __half g_h[(size_t)N_NODES * FEAT];      // fp16: deg_out^-1/2 * x  (51MB)
__device__ __half g_Wt[FEAT * FEAT];                // fp16 W transposed [n][k]
__device__ int    g_cnt_src[N_NODES];
__device__ int    g_cnt_dst[N_NODES];
__device__ int    g_off[N_NODES + 1];
__device__ int    g_cursor[N_NODES];
__device__ int    g_bsum[SCAN_NB];
__device__ int    g_csr_src[N_EDGES];

// ---------------- K0: zero counters ---------------------------------------
__global__ void k_zero_counters() {
    for (int i = blockIdx.x * blockDim.x + threadIdx.x;
         i < N_NODES; i += gridDim.x * blockDim.x) {
        g_cnt_src[i] = 0;
        g_cnt_dst[i] = 0;
    }
}

// ---------------- K1: degree histograms ------------------------------------
__global__ void k_hist(const int* __restrict__ src, const int* __restrict__ dst) {
    for (int e = blockIdx.x * blockDim.x + threadIdx.x;
         e < N_EDGES; e += gridDim.x * blockDim.x) {
        atomicAdd(&g_cnt_src[__ldg(&src[e])], 1);
        atomicAdd(&g_cnt_dst[__ldg(&dst[e])], 1);
    }
}

// ---------------- K2a: block-local exclusive scan of cnt_dst ---------------
__global__ void k_scan1() {
    __shared__ int s[SCAN_B];
    const int t = threadIdx.x;
    const int g = blockIdx.x * SCAN_B + t;
    int v = (g < N_NODES) ? g_cnt_dst[g] : 0;
    s[t] = v;
    __syncthreads();
#pragma unroll
    for (int off = 1; off < SCAN_B; off <<= 1) {
        int u = (t >= off) ? s[t - off] : 0;
        __syncthreads();
        s[t] += u;
        __syncthreads();
    }
    if (g < N_NODES) g_off[g] = s[t] - v;        // exclusive prefix (local)
    if (t == SCAN_B - 1) g_bsum[blockIdx.x] = s[t];
}

// ---------------- K2b: scan the 98 block sums ------------------------------
__global__ void k_scan2() {
    __shared__ int s[128];
    const int t = threadIdx.x;
    int v = (t < SCAN_NB) ? g_bsum[t] : 0;
    s[t] = v;
    __syncthreads();
#pragma unroll
    for (int off = 1; off < 128; off <<= 1) {
        int u = (t >= off) ? s[t - off] : 0;
        __syncthreads();
        s[t] += u;
        __syncthreads();
    }
    if (t < SCAN_NB) g_bsum[t] = s[t] - v;       // exclusive block offsets
    if (t == 0) g_off[N_NODES] = N_EDGES;
}

// ---------------- K2c: apply block offsets, init cursors -------------------
__global__ void k_scan3() {
    int g = blockIdx.x * blockDim.x + threadIdx.x;
    if (g < N_NODES) {
        int o = g_off[g] + g_bsum[g >> 10];      // SCAN_B = 1024
        g_off[g]    = o;
        g_cursor[g] = o;
    }
}

// ---------------- K3: build CSR (src ids grouped by dst) -------------------
__global__ void k_build(const int* __restrict__ src, const int* __restrict__ dst) {
    for (int e = blockIdx.x * blockDim.x + threadIdx.x;
         e < N_EDGES; e += gridDim.x * blockDim.x) {
        int d = __ldg(&dst[e]);
        int pos = atomicAdd(&g_cursor[d], 1);
        g_csr_src[pos] = __ldg(&src[e]);
    }
}

// ---------------- K4: h = fp16( x * rsqrt(max(deg_out,1)) ) ----------------
__global__ void k_scale_src(const float4* __restrict__ x) {
    const int n8 = N_NODES * FEAT8;   // 3.2M uint4 units
    for (int i = blockIdx.x * blockDim.x + threadIdx.x;
         i < n8; i += gridDim.x * blockDim.x) {
        int row = i >> 5;             // FEAT8 = 32
        float s = rsqrtf(fmaxf((float)__ldg(&g_cnt_src[row]), 1.f));
        float4 a = __ldg(&x[i * 2]);
        float4 b = __ldg(&x[i * 2 + 1]);
        union { uint4 u; __half2 h[4]; } o;
        o.h[0] = __floats2half2_rn(a.x * s, a.y * s);
        o.h[1] = __floats2half2_rn(a.z * s, a.w * s);
        o.h[2] = __floats2half2_rn(b.x * s, b.y * s);
        o.h[3] = __floats2half2_rn(b.z * s, b.w * s);
        ((uint4*)g_h)[i] = o.u;
    }
}

// ---------------- K5: convert W -> fp16 transposed [n][k] ------------------
__global__ void k_conv_w(const float* __restrict__ W) {
    int i = blockIdx.x * blockDim.x + threadIdx.x;   // i = k*FEAT + n
    if (i < FEAT * FEAT) {
        int k = i >> 8, n = i & 255;
        g_Wt[n * FEAT + k] = __float2half(__ldg(&W[i]));
    }
}

// ---------------- K6: MEGA — gather-aggregate + GEMM + bias/relu/L2norm ----
// Block owns 64 full rows. Phase 1: 8 warps gather 8 rows each into resident
// smem A tile (fp32 accum -> fp16). Phase 2: TC GEMM vs streamed W tiles.
// Phase 3: bias+relu+row-L2-normalize epilogue (all in regs/smem).
#define BM 64
#define BK 16
#define A_LD 264   // 256 + 8 pad: fragment banks = (4*lg + lt) -> conflict-free
#define B_LD 24    // 16 + 8 pad:  fragment banks = (12*lg + lt) -> conflict-free

__global__ void k_mega(const float* __restrict__ bias, float* __restrict__ out) {
    __shared__ __half As[BM][A_LD];       // 33792 B
    __shared__ __half Bs[FEAT][B_LD];     // 12288 B
    __shared__ float s_ss[BM];            //   256 B   (total 46336 B)

    const int row0 = blockIdx.x * BM;
    const int tid  = threadIdx.x;
    const int wid  = tid >> 5;
    const int lane = tid & 31;

    if (tid < BM) s_ss[tid] = 0.f;

    // ---- phase 1: gather-aggregate 8 rows per warp ----
    {
        const uint4* hp = (const uint4*)g_h;
#pragma unroll 1
        for (int i = 0; i < 8; i++) {
            int rl = wid * 8 + i;                 // 0..63
            int r = row0 + rl;
            float acc[8];
#pragma unroll
            for (int t = 0; t < 8; t++) acc[t] = 0.f;

            if (r < N_NODES) {
                int beg = __ldg(&g_off[r]);
                int end = __ldg(&g_off[r + 1]);
                int e = beg;
                for (; e + 4 <= end; e += 4) {
                    int s0 = __ldg(&g_csr_src[e]);
                    int s1 = __ldg(&g_csr_src[e + 1]);
                    int s2 = __ldg(&g_csr_src[e + 2]);
                    int s3 = __ldg(&g_csr_src[e + 3]);
                    uint4 u0 = __ldg(&hp[(size_t)s0 * FEAT8 + lane]);
                    uint4 u1 = __ldg(&hp[(size_t)s1 * FEAT8 + lane]);
                    uint4 u2 = __ldg(&hp[(size_t)s2 * FEAT8 + lane]);
                    uint4 u3 = __ldg(&hp[(size_t)s3 * FEAT8 + lane]);
                    const __half2* h0 = (const __half2*)&u0;
                    const __half2* h1 = (const __half2*)&u1;
                    const __half2* h2 = (const __half2*)&u2;
                    const __half2* h3 = (const __half2*)&u3;
#pragma unroll
                    for (int t = 0; t < 4; t++) {
                        float2 f0 = __half22float2(h0[t]);
                        float2 f1 = __half22float2(h1[t]);
                        float2 f2 = __half22float2(h2[t]);
                        float2 f3 = __half22float2(h3[t]);
                        acc[2 * t]     += (f0.x + f1.x) + (f2.x + f3.x);
                        acc[2 * t + 1] += (f0.y + f1.y) + (f2.y + f3.y);
                    }
                }
                for (; e < end; e++) {
                    int s0 = __ldg(&g_csr_src[e]);
                    uint4 u0 = __ldg(&hp[(size_t)s0 * FEAT8 + lane]);
                    const __half2* h0 = (const __half2*)&u0;
#pragma unroll
                    for (int t = 0; t < 4; t++) {
                        float2 f0 = __half22float2(h0[t]);
                        acc[2 * t]     += f0.x;
                        acc[2 * t + 1] += f0.y;
                    }
                }
                float sc = rsqrtf(fmaxf((float)(end - beg), 1.f));
#pragma unroll
                for (int t = 0; t < 8; t++) acc[t] *= sc;
            }
            union { uint4 u; __half2 h[4]; } o;
#pragma unroll
            for (int t = 0; t < 4; t++)
                o.h[t] = __floats2half2_rn(acc[2 * t], acc[2 * t + 1]);
            *(uint4*)&As[rl][lane * 8] = o.u;
        }
    }
    __syncthreads();

    // ---- phase 2: GEMM (A resident in smem, W streamed) ----
    const int warp_m = wid & 1;       // 0..1 -> 32-row slab
    const int warp_n = wid >> 1;      // 0..3 -> 64-col slab
    const int lg = lane >> 2;         // 0..7
    const int lt = lane & 3;          // 0..3

    float c[2][8][4];                 // [mt][nt][reg]
#pragma unroll
    for (int i = 0; i < 2; i++)
#pragma unroll
        for (int j = 0; j < 8; j++)
#pragma unroll
            for (int q = 0; q < 4; q++) c[i][j][q] = 0.f;

    for (int kt = 0; kt < FEAT; kt += BK) {
        // stage Bs: 256 n-rows x 16 halves = 512 uint4, 2 per thread
#pragma unroll
        for (int it = 0; it < 2; it++) {
            int i = tid + it * 256;           // 0..511
            int r = i >> 1;
            int seg = i & 1;
            uint4 v = __ldg((const uint4*)&g_Wt[(size_t)r * FEAT + kt + seg * 8]);
            *(uint4*)&Bs[r][seg * 8] = v;
        }
        __syncthreads();

        uint32_t a[2][4], b[8][2];
#pragma unroll
        for (int mt = 0; mt < 2; mt++) {
            int rb = warp_m * 32 + mt * 16;
            int kc = kt + lt * 2;
            a[mt][0] = *(const uint32_t*)&As[rb + lg][kc];
            a[mt][1] = *(const uint32_t*)&As[rb + lg + 8][kc];
            a[mt][2] = *(const uint32_t*)&As[rb + lg][kc + 8];
            a[mt][3] = *(const uint32_t*)&As[rb + lg + 8][kc + 8];
        }
#pragma unroll
        for (int nt = 0; nt < 8; nt++) {
            int cb = warp_n * 64 + nt * 8;
            b[nt][0] = *(const uint32_t*)&Bs[cb + lg][lt * 2];
            b[nt][1] = *(const uint32_t*)&Bs[cb + lg][lt * 2 + 8];
        }
#pragma unroll
        for (int mt = 0; mt < 2; mt++)
#pragma unroll
            for (int nt = 0; nt < 8; nt++) {
                asm volatile(
                    "mma.sync.aligned.m16n8k16.row.col.f32.f16.f16.f32 "
                    "{%0,%1,%2,%3}, {%4,%5,%6,%7}, {%8,%9}, {%0,%1,%2,%3};"
                    : "+f"(c[mt][nt][0]), "+f"(c[mt][nt][1]),
                      "+f"(c[mt][nt][2]), "+f"(c[mt][nt][3])
                    : "r"(a[mt][0]), "r"(a[mt][1]), "r"(a[mt][2]), "r"(a[mt][3]),
                      "r"(b[nt][0]), "r"(b[nt][1]));
            }
        __syncthreads();
    }

    // ---- phase 3a: bias + relu in regs, per-row sumsq partials ----
#pragma unroll
    for (int mt = 0; mt < 2; mt++) {
#pragma unroll
        for (int half_m = 0; half_m < 2; half_m++) {
            int rl = warp_m * 32 + mt * 16 + half_m * 8 + lg;   // 0..63
            float ss = 0.f;
#pragma unroll
            for (int nt = 0; nt < 8; nt++) {
                int col = warp_n * 64 + nt * 8 + lt * 2;
                float v0 = c[mt][nt][half_m * 2 + 0] + __ldg(&bias[col]);
                float v1 = c[mt][nt][half_m * 2 + 1] + __ldg(&bias[col + 1]);
                v0 = fmaxf(v0, 0.f);
                v1 = fmaxf(v1, 0.f);
                c[mt][nt][half_m * 2 + 0] = v0;
                c[mt][nt][half_m * 2 + 1] = v1;
                ss = fmaf(v0, v0, fmaf(v1, v1, ss));
            }
            atomicAdd(&s_ss[rl], ss);
        }
    }
    __syncthreads();

    // ---- phase 3b: normalize + store ----
#pragma unroll
    for (int mt = 0; mt < 2; mt++) {
#pragma unroll
        for (int half_m = 0; half_m < 2; half_m++) {
            int rl = warp_m * 32 + mt * 16 + half_m * 8 + lg;
            int row = row0 + rl;
            if (row >= N_NODES) continue;
            float inv = 1.f / fmaxf(sqrtf(s_ss[rl]), EPS);
#pragma unroll
            for (int nt = 0; nt < 8; nt++) {
                int col = warp_n * 64 + nt * 8 + lt * 2;
                float2 v;
                v.x = c[mt][nt][half_m * 2 + 0] * inv;
                v.y = c[mt][nt][half_m * 2 + 1] * inv;
                *(float2*)&out[(size_t)row * FEAT + col] = v;
            }
        }
    }
}

// ---------------- launch ----------------------------------------------------
extern "C" void kernel_launch(void* const* d_in, const int* in_sizes, int n_in,
                              void* d_out, int out_size) {
    const float* x   = (const float*)d_in[0];
    const float* W   = (const float*)d_in[1];
    const float* b   = (const float*)d_in[2];
    const int*   src = (const int*)d_in[3];
    const int*   dst = (const int*)d_in[4];
    float* out = (float*)d_out;

    k_zero_counters<<<(N_NODES + 255) / 256, 256>>>();
    k_hist<<<(N_EDGES + 255) / 256, 256>>>(src, dst);
    k_conv_w<<<(FEAT * FEAT + 255) / 256, 256>>>(W);

    k_scan1<<<SCAN_NB, SCAN_B>>>();
    k_scan2<<<1, 128>>>();
    k_scan3<<<(N_NODES + 255) / 256, 256>>>();

    k_build<<<(N_EDGES + 255) / 256, 256>>>(src, dst);

    const int n8 = N_NODES * FEAT8;
    k_scale_src<<<(n8 + 255) / 256, 256>>>((const float4*)x);

    k_mega<<<(N_NODES + BM - 1) / BM, 256>>>(b, out);   // 1563 blocks
}

// round 12
// speedup vs baseline: 1.3570x; 1.3570x over previous
#include <cuda_runtime.h>
#include <cuda_fp16.h>
#include <cuda_bf16.h>
#include <cstdint>
#include <cstddef>

#define N_NODES 100000
#define N_EDGES 3200000
#define FEAT 256
#define FEAT8 (FEAT / 8)          // uint4 (8 halves) units per row = 32
#define EPS 1e-12f
#define SCAN_B 1024
#define SCAN_NB ((N_NODES + SCAN_B - 1) / SCAN_B)   // 98

// ---------------- device scratch (no allocations allowed) ----------------
__device__ __half g_h[(size_t)N_NODES * FEAT];      // fp16: deg_out^-1/2 * x  (51MB)
__device__ __half g_agg[(size_t)N_NODES * FEAT];    // fp16: aggregated+scaled (51MB)
__device__ __half g_Wt[FEAT * FEAT];                // fp16 W transposed [n][k]
__device__ int    g_cnt_src[N_NODES];
__device__ int    g_cnt_dst[N_NODES];
__device__ int    g_off[N_NODES + 1];
__device__ int    g_cursor[N_NODES];
__device__ int    g_bsum[SCAN_NB];
__device__ int    g_csr_src[N_EDGES];

// ---------------- K0: zero counters ---------------------------------------
__global__ void k_zero_counters() {
    for (int i = blockIdx.x * blockDim.x + threadIdx.x;
         i < N_NODES; i += gridDim.x * blockDim.x) {
        g_cnt_src[i] = 0;
        g_cnt_dst[i] = 0;
    }
}

// ---------------- K1: dst-degree histogram only ----------------------------
__global__ void k_hist(const int* __restrict__ dst) {
    for (int e = blockIdx.x * blockDim.x + threadIdx.x;
         e < N_EDGES; e += gridDim.x * blockDim.x) {
        atomicAdd(&g_cnt_dst[__ldg(&dst[e])], 1);
    }
}

// ---------------- K2a: block-local exclusive scan of cnt_dst ---------------
__global__ void k_scan1() {
    __shared__ int s[SCAN_B];
    const int t = threadIdx.x;
    const int g = blockIdx.x * SCAN_B + t;
    int v = (g < N_NODES) ? g_cnt_dst[g] : 0;
    s[t] = v;
    __syncthreads();
#pragma unroll
    for (int off = 1; off < SCAN_B; off <<= 1) {
        int u = (t >= off) ? s[t - off] : 0;
        __syncthreads();
        s[t] += u;
        __syncthreads();
    }
    if (g < N_NODES) g_off[g] = s[t] - v;        // exclusive prefix (local)
    if (t == SCAN_B - 1) g_bsum[blockIdx.x] = s[t];
}

// ---------------- K2b: scan the 98 block sums ------------------------------
__global__ void k_scan2() {
    __shared__ int s[128];
    const int t = threadIdx.x;
    int v = (t < SCAN_NB) ? g_bsum[t] : 0;
    s[t] = v;
    __syncthreads();
#pragma unroll
    for (int off = 1; off < 128; off <<= 1) {
        int u = (t >= off) ? s[t - off] : 0;
        __syncthreads();
        s[t] += u;
        __syncthreads();
    }
    if (t < SCAN_NB) g_bsum[t] = s[t] - v;       // exclusive block offsets
    if (t == 0) g_off[N_NODES] = N_EDGES;
}

// ---------------- K2c: apply block offsets, init cursors -------------------
__global__ void k_scan3() {
    int g = blockIdx.x * blockDim.x + threadIdx.x;
    if (g < N_NODES) {
        int o = g_off[g] + g_bsum[g >> 10];      // SCAN_B = 1024
        g_off[g]    = o;
        g_cursor[g] = o;
    }
}

// ---------------- K3: build CSR + src-degree histogram ---------------------
__global__ void k_build(const int* __restrict__ src, const int* __restrict__ dst) {
    for (int e = blockIdx.x * blockDim.x + threadIdx.x;
         e < N_EDGES; e += gridDim.x * blockDim.x) {
        int s = __ldg(&src[e]);
        int d = __ldg(&dst[e]);
        atomicAdd(&g_cnt_src[s], 1);
        int pos = atomicAdd(&g_cursor[d], 1);
        g_csr_src[pos] = s;
    }
}

// ---------------- K4: h = fp16( x * rsqrt(max(deg_out,1)) ) ----------------
__global__ void k_scale_src(const float4* __restrict__ x) {
    const int n8 = N_NODES * FEAT8;   // 3.2M uint4 units
    for (int i = blockIdx.x * blockDim.x + threadIdx.x;
         i < n8; i += gridDim.x * blockDim.x) {
        int row = i >> 5;             // FEAT8 = 32
        float s = rsqrtf(fmaxf((float)__ldg(&g_cnt_src[row]), 1.f));
        float4 a = __ldg(&x[i * 2]);
        float4 b = __ldg(&x[i * 2 + 1]);
        union { uint4 u; __half2 h[4]; } o;
        o.h[0] = __floats2half2_rn(a.x * s, a.y * s);
        o.h[1] = __floats2half2_rn(a.z * s, a.w * s);
        o.h[2] = __floats2half2_rn(b.x * s, b.y * s);
        o.h[3] = __floats2half2_rn(b.z * s, b.w * s);
        ((uint4*)g_h)[i] = o.u;
    }
}

// ---------------- K5: convert W -> fp16 transposed [n][k] ------------------
__global__ void k_conv_w(const float* __restrict__ W) {
    int i = blockIdx.x * blockDim.x + threadIdx.x;   // i = k*FEAT + n
    if (i < FEAT * FEAT) {
        int k = i >> 8, n = i & 255;
        g_Wt[n * FEAT + k] = __float2half(__ldg(&W[i]));
    }
}

// ---------------- K6: gather-aggregate (fp32 acc) + right norm -> fp16 -----
// One warp per dst row; lane owns 8 halves (16B). Unroll-4 for MLP.
__global__ void k_aggregate() {
    int r = (int)((blockIdx.x * blockDim.x + threadIdx.x) >> 5);
    int lane = threadIdx.x & 31;
    if (r >= N_NODES) return;

    int beg = __ldg(&g_off[r]);
    int end = __ldg(&g_off[r + 1]);

    const uint4* hp = (const uint4*)g_h;
    float acc[8];
#pragma unroll
    for (int t = 0; t < 8; t++) acc[t] = 0.f;

    int e = beg;
    for (; e + 4 <= end; e += 4) {
        int s0 = __ldg(&g_csr_src[e]);
        int s1 = __ldg(&g_csr_src[e + 1]);
        int s2 = __ldg(&g_csr_src[e + 2]);
        int s3 = __ldg(&g_csr_src[e + 3]);
        uint4 u0 = __ldg(&hp[(size_t)s0 * FEAT8 + lane]);
        uint4 u1 = __ldg(&hp[(size_t)s1 * FEAT8 + lane]);
        uint4 u2 = __ldg(&hp[(size_t)s2 * FEAT8 + lane]);
        uint4 u3 = __ldg(&hp[(size_t)s3 * FEAT8 + lane]);
        const __half2* h0 = (const __half2*)&u0;
        const __half2* h1 = (const __half2*)&u1;
        const __half2* h2 = (const __half2*)&u2;
        const __half2* h3 = (const __half2*)&u3;
#pragma unroll
        for (int t = 0; t < 4; t++) {
            float2 f0 = __half22float2(h0[t]);
            float2 f1 = __half22float2(h1[t]);
            float2 f2 = __half22float2(h2[t]);
            float2 f3 = __half22float2(h3[t]);
            acc[2 * t]     += (f0.x + f1.x) + (f2.x + f3.x);
            acc[2 * t + 1] += (f0.y + f1.y) + (f2.y + f3.y);
        }
    }
    for (; e < end; e++) {
        int s0 = __ldg(&g_csr_src[e]);
        uint4 u0 = __ldg(&hp[(size_t)s0 * FEAT8 + lane]);
        const __half2* h0 = (const __half2*)&u0;
#pragma unroll
        for (int t = 0; t < 4; t++) {
            float2 f0 = __half22float2(h0[t]);
            acc[2 * t]     += f0.x;
            acc[2 * t + 1] += f0.y;
        }
    }

    float sc = rsqrtf(fmaxf((float)(end - beg), 1.f));
    union { uint4 u; __half2 h[4]; } o;
#pragma unroll
    for (int t = 0; t < 4; t++)
        o.h[t] = __floats2half2_rn(acc[2 * t] * sc, acc[2 * t + 1] * sc);
    ((uint4*)g_agg)[(size_t)r * FEAT8 + lane] = o.u;
}

// ---------------- K7: fused fp16 TC GEMM + bias + relu + L2 normalize ------
// out = l2norm_row( relu(agg @ W + b) ).  Block owns FULL rows:
// BM=64 rows x BN=256 (=FEAT) cols, BK=32. 8 warps: 2 m x 4 n, warp 32x64.
#define BM 64
#define BN 256
#define BK 32
#define APAD 8

__global__ void k_gemm_fused(const float* __restrict__ bias, float* __restrict__ out) {
    __shared__ __half As[BM][BK + APAD];
    __shared__ __half Bs[BN][BK + APAD];
    __shared__ float s_ss[BM];

    const int row0 = blockIdx.x * BM;
    const int tid  = threadIdx.x;
    const int wid  = tid >> 5;
    const int lane = tid & 31;
    const int warp_m = wid & 1;       // 0..1 -> 32-row slab
    const int warp_n = wid >> 1;      // 0..3 -> 64-col slab
    const int lg = lane >> 2;         // 0..7
    const int lt = lane & 3;          // 0..3

    if (tid < BM) s_ss[tid] = 0.f;

    float c[2][8][4];                 // [mt][nt][reg]
#pragma unroll
    for (int i = 0; i < 2; i++)
#pragma unroll
        for (int j = 0; j < 8; j++)
#pragma unroll
            for (int q = 0; q < 4; q++) c[i][j][q] = 0.f;

    const uint4 zero4 = make_uint4(0, 0, 0, 0);

    for (int kt = 0; kt < FEAT; kt += BK) {
        // A tile: 64 rows x 32 halves = 256 uint4, 1 per thread
        {
            int r = tid >> 2;
            int seg = tid & 3;
            uint4 v = zero4;
            int grow = row0 + r;
            if (grow < N_NODES)
                v = __ldg((const uint4*)&g_agg[(size_t)grow * FEAT + kt + seg * 8]);
            *(uint4*)&As[r][seg * 8] = v;
        }
        // B tile: 256 n-rows x 32 halves = 1024 uint4, 4 per thread
#pragma unroll
        for (int it = 0; it < 4; it++) {
            int i = tid + it * 256;           // 0..1023
            int r = i >> 2;
            int seg = i & 3;
            uint4 v = __ldg((const uint4*)&g_Wt[(size_t)r * FEAT + kt + seg * 8]);
            *(uint4*)&Bs[r][seg * 8] = v;
        }
        __syncthreads();

#pragma unroll
        for (int ks = 0; ks < 2; ks++) {      // two k=16 steps per BK=32
            uint32_t a[2][4], b[8][2];
#pragma unroll
            for (int mt = 0; mt < 2; mt++) {
                int rb = warp_m * 32 + mt * 16;
                int kc = ks * 16 + lt * 2;
                a[mt][0] = *(const uint32_t*)&As[rb + lg][kc];
                a[mt][1] = *(const uint32_t*)&As[rb + lg + 8][kc];
                a[mt][2] = *(const uint32_t*)&As[rb + lg][kc + 8];
                a[mt][3] = *(const uint32_t*)&As[rb + lg + 8][kc + 8];
            }
#pragma unroll
            for (int nt = 0; nt < 8; nt++) {
                int cb = warp_n * 64 + nt * 8;
                int kc = ks * 16 + lt * 2;
                b[nt][0] = *(const uint32_t*)&Bs[cb + lg][kc];
                b[nt][1] = *(const uint32_t*)&Bs[cb + lg][kc + 8];
            }
#pragma unroll
            for (int mt = 0; mt < 2; mt++)
#pragma unroll
                for (int nt = 0; nt < 8; nt++) {
                    asm volatile(
                        "mma.sync.aligned.m16n8k16.row.col.f32.f16.f16.f32 "
                        "{%0,%1,%2,%3}, {%4,%5,%6,%7}, {%8,%9}, {%0,%1,%2,%3};"
                        : "+f"(c[mt][nt][0]), "+f"(c[mt][nt][1]),
                          "+f"(c[mt][nt][2]), "+f"(c[mt][nt][3])
                        : "r"(a[mt][0]), "r"(a[mt][1]), "r"(a[mt][2]), "r"(a[mt][3]),
                          "r"(b[nt][0]), "r"(b[nt][1]));
                }
        }
        __syncthreads();
    }

    // ---- epilogue phase 1: bias + relu in regs, per-row sumsq partials ----
#pragma unroll
    for (int mt = 0; mt < 2; mt++) {
#pragma unroll
        for (int half_m = 0; half_m < 2; half_m++) {
            int rl = warp_m * 32 + mt * 16 + half_m * 8 + lg;   // 0..63
            float ss = 0.f;
#pragma unroll
            for (int nt = 0; nt < 8; nt++) {
                int col = warp_n * 64 + nt * 8 + lt * 2;
                float v0 = c[mt][nt][half_m * 2 + 0] + __ldg(&bias[col]);
                float v1 = c[mt][nt][half_m * 2 + 1] + __ldg(&bias[col + 1]);
                v0 = fmaxf(v0, 0.f);
                v1 = fmaxf(v1, 0.f);
                c[mt][nt][half_m * 2 + 0] = v0;
                c[mt][nt][half_m * 2 + 1] = v1;
                ss = fmaf(v0, v0, fmaf(v1, v1, ss));
            }
            atomicAdd(&s_ss[rl], ss);
        }
    }
    __syncthreads();

    // ---- epilogue phase 2: normalize + store ----
#pragma unroll
    for (int mt = 0; mt < 2; mt++) {
#pragma unroll
        for (int half_m = 0; half_m < 2; half_m++) {
            int rl = warp_m * 32 + mt * 16 + half_m * 8 + lg;
            int row = row0 + rl;
            if (row >= N_NODES) continue;
            float inv = 1.f / fmaxf(sqrtf(s_ss[rl]), EPS);
#pragma unroll
            for (int nt = 0; nt < 8; nt++) {
                int col = warp_n * 64 + nt * 8 + lt * 2;
                float2 v;
                v.x = c[mt][nt][half_m * 2 + 0] * inv;
                v.y = c[mt][nt][half_m * 2 + 1] * inv;
                *(float2*)&out[(size_t)row * FEAT + col] = v;
            }
        }
    }
}

// ---------------- launch ----------------------------------------------------
extern "C" void kernel_launch(void* const* d_in, const int* in_sizes, int n_in,
                              void* d_out, int out_size) {
    const float* x   = (const float*)d_in[0];
    const float* W   = (const float*)d_in[1];
    const float* b   = (const float*)d_in[2];
    const int*   src = (const int*)d_in[3];
    const int*   dst = (const int*)d_in[4];
    float* out = (float*)d_out;

    k_zero_counters<<<(N_NODES + 255) / 256, 256>>>();
    k_hist<<<(N_EDGES + 255) / 256, 256>>>(dst);
    k_conv_w<<<(FEAT * FEAT + 255) / 256, 256>>>(W);

    k_scan1<<<SCAN_NB, SCAN_B>>>();
    k_scan2<<<1, 128>>>();
    k_scan3<<<(N_NODES + 255) / 256, 256>>>();

    k_build<<<(N_EDGES + 255) / 256, 256>>>(src, dst);

    const int n8 = N_NODES * FEAT8;
    k_scale_src<<<(n8 + 255) / 256, 256>>>((const float4*)x);

    k_aggregate<<<(N_NODES * 32 + 255) / 256, 256>>>();   // 1 warp / row

    k_gemm_fused<<<(N_NODES + BM - 1) / BM, 256>>>(b, out);   // 1563 blocks
}

// round 13
// speedup vs baseline: 1.4860x; 1.0950x over previous
#include <cuda_runtime.h>
#include <cuda_fp16.h>
#include <cuda_bf16.h>
#include <cstdint>
#include <cstddef>

#define N_NODES 100000
#define N_EDGES 3200000
#define FEAT 256
#define FEAT8 (FEAT / 8)          // uint4 (8 halves) units per row = 32
#define EPS 1e-12f
#define SCAN_B 1024
#define SCAN_NB ((N_NODES + SCAN_B - 1) / SCAN_B)   // 98

// ---------------- device scratch (no allocations allowed) ----------------
__device__ __half g_h[(size_t)N_NODES * FEAT];      // fp16: deg_out^-1/2 * x  (51MB)
__device__ __half g_agg[(size_t)N_NODES * FEAT];    // fp16: aggregated+scaled (51MB)
__device__ __half g_Wt[FEAT * FEAT];                // fp16 W transposed [n][k]
__device__ int    g_cnt_src[N_NODES];
__device__ int    g_cnt_dst[N_NODES];
__device__ int    g_off[N_NODES + 1];
__device__ int    g_cursor[N_NODES];
__device__ int    g_bsum[SCAN_NB];
__device__ int    g_csr_src[N_EDGES];

// ---------------- K0: zero counters ---------------------------------------
__global__ void k_zero_counters() {
    for (int i = blockIdx.x * blockDim.x + threadIdx.x;
         i < N_NODES; i += gridDim.x * blockDim.x) {
        g_cnt_src[i] = 0;
        g_cnt_dst[i] = 0;
    }
}

// ---------------- K1: degree histograms ------------------------------------
__global__ void k_hist(const int* __restrict__ src, const int* __restrict__ dst) {
    for (int e = blockIdx.x * blockDim.x + threadIdx.x;
         e < N_EDGES; e += gridDim.x * blockDim.x) {
        atomicAdd(&g_cnt_src[__ldg(&src[e])], 1);
        atomicAdd(&g_cnt_dst[__ldg(&dst[e])], 1);
    }
}

// ---------------- K2a: block-local exclusive scan of cnt_dst ---------------
__global__ void k_scan1() {
    __shared__ int s[SCAN_B];
    const int t = threadIdx.x;
    const int g = blockIdx.x * SCAN_B + t;
    int v = (g < N_NODES) ? g_cnt_dst[g] : 0;
    s[t] = v;
    __syncthreads();
#pragma unroll
    for (int off = 1; off < SCAN_B; off <<= 1) {
        int u = (t >= off) ? s[t - off] : 0;
        __syncthreads();
        s[t] += u;
        __syncthreads();
    }
    if (g < N_NODES) g_off[g] = s[t] - v;        // exclusive prefix (local)
    if (t == SCAN_B - 1) g_bsum[blockIdx.x] = s[t];
}

// ---------------- K2b: scan the 98 block sums ------------------------------
__global__ void k_scan2() {
    __shared__ int s[128];
    const int t = threadIdx.x;
    int v = (t < SCAN_NB) ? g_bsum[t] : 0;
    s[t] = v;
    __syncthreads();
#pragma unroll
    for (int off = 1; off < 128; off <<= 1) {
        int u = (t >= off) ? s[t - off] : 0;
        __syncthreads();
        s[t] += u;
        __syncthreads();
    }
    if (t < SCAN_NB) g_bsum[t] = s[t] - v;       // exclusive block offsets
    if (t == 0) g_off[N_NODES] = N_EDGES;
}

// ---------------- K2c: apply block offsets, init cursors -------------------
__global__ void k_scan3() {
    int g = blockIdx.x * blockDim.x + threadIdx.x;
    if (g < N_NODES) {
        int o = g_off[g] + g_bsum[g >> 10];      // SCAN_B = 1024
        g_off[g]    = o;
        g_cursor[g] = o;
    }
}

// ---------------- K3: build CSR (src ids grouped by dst) -------------------
__global__ void k_build(const int* __restrict__ src, const int* __restrict__ dst) {
    for (int e = blockIdx.x * blockDim.x + threadIdx.x;
         e < N_EDGES; e += gridDim.x * blockDim.x) {
        int d = __ldg(&dst[e]);
        int pos = atomicAdd(&g_cursor[d], 1);
        g_csr_src[pos] = __ldg(&src[e]);
    }
}

// ---------------- K4: h = fp16( x * rsqrt(max(deg_out,1)) ) ----------------
__global__ void k_scale_src(const float4* __restrict__ x) {
    const int n8 = N_NODES * FEAT8;   // 3.2M uint4 units
    for (int i = blockIdx.x * blockDim.x + threadIdx.x;
         i < n8; i += gridDim.x * blockDim.x) {
        int row = i >> 5;             // FEAT8 = 32
        float s = rsqrtf(fmaxf((float)__ldg(&g_cnt_src[row]), 1.f));
        float4 a = __ldg(&x[i * 2]);
        float4 b = __ldg(&x[i * 2 + 1]);
        union { uint4 u; __half2 h[4]; } o;
        o.h[0] = __floats2half2_rn(a.x * s, a.y * s);
        o.h[1] = __floats2half2_rn(a.z * s, a.w * s);
        o.h[2] = __floats2half2_rn(b.x * s, b.y * s);
        o.h[3] = __floats2half2_rn(b.z * s, b.w * s);
        ((uint4*)g_h)[i] = o.u;
    }
}

// ---------------- K5: convert W -> fp16 transposed [n][k] ------------------
__global__ void k_conv_w(const float* __restrict__ W) {
    int i = blockIdx.x * blockDim.x + threadIdx.x;   // i = k*FEAT + n
    if (i < FEAT * FEAT) {
        int k = i >> 8, n = i & 255;
        g_Wt[n * FEAT + k] = __float2half(__ldg(&W[i]));
    }
}

// ---------------- K6: gather-aggregate (fp32 acc) + right norm -> fp16 -----
// One warp per dst row; lane owns 8 halves (16B).  (R10 config: unroll-2)
__global__ void k_aggregate() {
    int r = (int)((blockIdx.x * blockDim.x + threadIdx.x) >> 5);
    int lane = threadIdx.x & 31;
    if (r >= N_NODES) return;

    int beg = __ldg(&g_off[r]);
    int end = __ldg(&g_off[r + 1]);

    const uint4* hp = (const uint4*)g_h;
    float acc[8];
#pragma unroll
    for (int t = 0; t < 8; t++) acc[t] = 0.f;

    int e = beg;
    for (; e + 2 <= end; e += 2) {
        int s0 = __ldg(&g_csr_src[e]);
        int s1 = __ldg(&g_csr_src[e + 1]);
        uint4 u0 = __ldg(&hp[(size_t)s0 * FEAT8 + lane]);
        uint4 u1 = __ldg(&hp[(size_t)s1 * FEAT8 + lane]);
        const __half2* h0 = (const __half2*)&u0;
        const __half2* h1 = (const __half2*)&u1;
#pragma unroll
        for (int t = 0; t < 4; t++) {
            float2 f0 = __half22float2(h0[t]);
            float2 f1 = __half22float2(h1[t]);
            acc[2 * t]     += f0.x + f1.x;
            acc[2 * t + 1] += f0.y + f1.y;
        }
    }
    if (e < end) {
        int s0 = __ldg(&g_csr_src[e]);
        uint4 u0 = __ldg(&hp[(size_t)s0 * FEAT8 + lane]);
        const __half2* h0 = (const __half2*)&u0;
#pragma unroll
        for (int t = 0; t < 4; t++) {
            float2 f0 = __half22float2(h0[t]);
            acc[2 * t]     += f0.x;
            acc[2 * t + 1] += f0.y;
        }
    }

    float sc = rsqrtf(fmaxf((float)(end - beg), 1.f));
    union { uint4 u; __half2 h[4]; } o;
#pragma unroll
    for (int t = 0; t < 4; t++)
        o.h[t] = __floats2half2_rn(acc[2 * t] * sc, acc[2 * t + 1] * sc);
    ((uint4*)g_agg)[(size_t)r * FEAT8 + lane] = o.u;
}

// ---------------- K7: fused GEMM (2-stage cp.async) + bias/relu/L2norm -----
// BM=64 rows x BN=256 cols, BK=32, double-buffered smem tiles.
#define BM 64
#define BN 256
#define BK 32
#define A_LD 40      // 32 + 8 pad: fragment banks 20*lg+lt cover 0..31
#define B_LD 40
#define NT (FEAT / BK)   // 8
#define SMEM_BYTES ((2 * BM * A_LD + 2 * BN * B_LD) * 2 + BM * 4)  // 51456

__device__ __forceinline__ void cp_async16(uint32_t d, const void* g, int src_bytes) {
    asm volatile("cp.async.cg.shared.global [%0], [%1], 16, %2;"
                 :: "r"(d), "l"(g), "r"(src_bytes));
}

__global__ void k_gemm_fused(const float* __restrict__ bias, float* __restrict__ out) {
    extern __shared__ __half sm[];
    __half* As = sm;                              // [2][BM][A_LD]
    __half* Bs = sm + 2 * BM * A_LD;              // [2][BN][B_LD]
    float*  s_ss = (float*)(Bs + 2 * BN * B_LD);  // [BM]

    const int row0 = blockIdx.x * BM;
    const int tid  = threadIdx.x;
    const int wid  = tid >> 5;
    const int lane = tid & 31;
    const int warp_m = wid & 1;       // 0..1 -> 32-row slab
    const int warp_n = wid >> 1;      // 0..3 -> 64-col slab
    const int lg = lane >> 2;         // 0..7
    const int lt = lane & 3;          // 0..3

    if (tid < BM) s_ss[tid] = 0.f;

    // per-thread load coords
    const int a_r   = tid >> 2;            // 0..63
    const int a_seg = tid & 3;             // 0..3 (x8 halves)
    const int a_row = row0 + a_r;
    const int a_sb  = (a_row < N_NODES) ? 16 : 0;
    const __half* a_g0 = &g_agg[(size_t)min(a_row, N_NODES - 1) * FEAT + a_seg * 8];

    float c[2][8][4];
#pragma unroll
    for (int i = 0; i < 2; i++)
#pragma unroll
        for (int j = 0; j < 8; j++)
#pragma unroll
            for (int q = 0; q < 4; q++) c[i][j][q] = 0.f;

    // stage loader: kt = k offset, st = buffer index
    auto load_stage = [&](int kt, int st) {
        uint32_t da = (uint32_t)__cvta_generic_to_shared(
            &As[st * BM * A_LD + a_r * A_LD + a_seg * 8]);
        cp_async16(da, a_g0 + kt, a_sb);
#pragma unroll
        for (int it = 0; it < 4; it++) {
            int i = tid + it * 256;            // 0..1023
            int r = i >> 2;
            int seg = i & 3;
            uint32_t db = (uint32_t)__cvta_generic_to_shared(
                &Bs[st * BN * B_LD + r * B_LD + seg * 8]);
            cp_async16(db, &g_Wt[(size_t)r * FEAT + kt + seg * 8], 16);
        }
        asm volatile("cp.async.commit_group;");
    };

    load_stage(0, 0);

    for (int i = 0; i < NT; i++) {
        if (i + 1 < NT) {
            load_stage((i + 1) * BK, (i + 1) & 1);
            asm volatile("cp.async.wait_group 1;");
        } else {
            asm volatile("cp.async.wait_group 0;");
        }
        __syncthreads();

        const __half* Ab = As + (i & 1) * BM * A_LD;
        const __half* Bb = Bs + (i & 1) * BN * B_LD;

#pragma unroll
        for (int ks = 0; ks < 2; ks++) {      // two k=16 steps per BK=32
            uint32_t a[2][4], b[8][2];
#pragma unroll
            for (int mt = 0; mt < 2; mt++) {
                int rb = warp_m * 32 + mt * 16;
                int kc = ks * 16 + lt * 2;
                a[mt][0] = *(const uint32_t*)&Ab[(rb + lg) * A_LD + kc];
                a[mt][1] = *(const uint32_t*)&Ab[(rb + lg + 8) * A_LD + kc];
                a[mt][2] = *(const uint32_t*)&Ab[(rb + lg) * A_LD + kc + 8];
                a[mt][3] = *(const uint32_t*)&Ab[(rb + lg + 8) * A_LD + kc + 8];
            }
#pragma unroll
            for (int nt = 0; nt < 8; nt++) {
                int cb = warp_n * 64 + nt * 8;
                int kc = ks * 16 + lt * 2;
                b[nt][0] = *(const uint32_t*)&Bb[(cb + lg) * B_LD + kc];
                b[nt][1] = *(const uint32_t*)&Bb[(cb + lg) * B_LD + kc + 8];
            }
#pragma unroll
            for (int mt = 0; mt < 2; mt++)
#pragma unroll
                for (int nt = 0; nt < 8; nt++) {
                    asm volatile(
                        "mma.sync.aligned.m16n8k16.row.col.f32.f16.f16.f32 "
                        "{%0,%1,%2,%3}, {%4,%5,%6,%7}, {%8,%9}, {%0,%1,%2,%3};"
                        : "+f"(c[mt][nt][0]), "+f"(c[mt][nt][1]),
                          "+f"(c[mt][nt][2]), "+f"(c[mt][nt][3])
                        : "r"(a[mt][0]), "r"(a[mt][1]), "r"(a[mt][2]), "r"(a[mt][3]),
                          "r"(b[nt][0]), "r"(b[nt][1]));
                }
        }
        __syncthreads();
    }

    // ---- epilogue phase 1: bias + relu in regs, per-row sumsq partials ----
#pragma unroll
    for (int mt = 0; mt < 2; mt++) {
#pragma unroll
        for (int half_m = 0; half_m < 2; half_m++) {
            int rl = warp_m * 32 + mt * 16 + half_m * 8 + lg;   // 0..63
            float ss = 0.f;
#pragma unroll
            for (int nt = 0; nt < 8; nt++) {
                int col = warp_n * 64 + nt * 8 + lt * 2;
                float v0 = c[mt][nt][half_m * 2 + 0] + __ldg(&bias[col]);
                float v1 = c[mt][nt][half_m * 2 + 1] + __ldg(&bias[col + 1]);
                v0 = fmaxf(v0, 0.f);
                v1 = fmaxf(v1, 0.f);
                c[mt][nt][half_m * 2 + 0] = v0;
                c[mt][nt][half_m * 2 + 1] = v1;
                ss = fmaf(v0, v0, fmaf(v1, v1, ss));
            }
            atomicAdd(&s_ss[rl], ss);
        }
    }
    __syncthreads();

    // ---- epilogue phase 2: normalize + store ----
#pragma unroll
    for (int mt = 0; mt < 2; mt++) {
#pragma unroll
        for (int half_m = 0; half_m < 2; half_m++) {
            int rl = warp_m * 32 + mt * 16 + half_m * 8 + lg;
            int row = row0 + rl;
            if (row >= N_NODES) continue;
            float inv = 1.f / fmaxf(sqrtf(s_ss[rl]), EPS);
#pragma unroll
            for (int nt = 0; nt < 8; nt++) {
                int col = warp_n * 64 + nt * 8 + lt * 2;
                float2 v;
                v.x = c[mt][nt][half_m * 2 + 0] * inv;
                v.y = c[mt][nt][half_m * 2 + 1] * inv;
                *(float2*)&out[(size_t)row * FEAT + col] = v;
            }
        }
    }
}

// ---------------- launch ----------------------------------------------------
extern "C" void kernel_launch(void* const* d_in, const int* in_sizes, int n_in,
                              void* d_out, int out_size) {
    const float* x   = (const float*)d_in[0];
    const float* W   = (const float*)d_in[1];
    const float* b   = (const float*)d_in[2];
    const int*   src = (const int*)d_in[3];
    const int*   dst = (const int*)d_in[4];
    float* out = (float*)d_out;

    static bool attr_set = false;
    if (!attr_set) {
        cudaFuncSetAttribute(k_gemm_fused,
                             cudaFuncAttributeMaxDynamicSharedMemorySize,
                             SMEM_BYTES);
        attr_set = true;
    }

    k_zero_counters<<<(N_NODES + 255) / 256, 256>>>();
    k_hist<<<(N_EDGES + 255) / 256, 256>>>(src, dst);
    k_conv_w<<<(FEAT * FEAT + 255) / 256, 256>>>(W);

    k_scan1<<<SCAN_NB, SCAN_B>>>();
    k_scan2<<<1, 128>>>();
    k_scan3<<<(N_NODES + 255) / 256, 256>>>();

    k_build<<<(N_EDGES + 255) / 256, 256>>>(src, dst);

    const int n8 = N_NODES * FEAT8;
    k_scale_src<<<(n8 + 255) / 256, 256>>>((const float4*)x);

    k_aggregate<<<(N_NODES * 32 + 255) / 256, 256>>>();   // 1 warp / row

    k_gemm_fused<<<(N_NODES + BM - 1) / BM, 256, SMEM_BYTES>>>(b, out);
}